// round 5
// baseline (speedup 1.0000x reference)
#include <cuda_runtime.h>
#include <cstdint>

// ============================================================================
// Problem constants
// ============================================================================
static constexpr int E_   = 16;
static constexpr int NTOK = 2048;
static constexpr int DDIM = 1024;
static constexpr int HDIM = 4096;

// Tile config: 128x128 CTA tile, 256 threads (8 warps, 2m x 4n of 64x32 tiles)
static constexpr int BM = 128;
static constexpr int BN = 128;
static constexpr int BK = 32;              // 32 fp32 = 128 B rows
static constexpr int STAGES = 3;
static constexpr int THREADS = 256;
static constexpr int MT = NTOK / BM;       // 16 M-tiles

static constexpr int A_BYTES     = BM * 128;             // 16 KB / stage
static constexpr int B_BYTES     = BN * 128;             // 16 KB / stage
static constexpr int STAGE_BYTES = A_BYTES + B_BYTES;    // 32 KB
static constexpr int SMEM_TOTAL  = STAGES * STAGE_BYTES; // 96 KB  (2 CTAs/SM)

// Hidden activations (no cudaMalloc allowed -> device global)
__device__ float g_hidden[(size_t)E_ * NTOK * HDIM];

// ============================================================================
// PTX helpers (plain sm_80+ features only — ptxas target is sm_103 WITHOUT 'a')
// ============================================================================
__device__ __forceinline__ uint32_t smem_u32(const void* p) {
    uint32_t a;
    asm("{ .reg .u64 t; cvta.to.shared.u64 t, %1; cvt.u32.u64 %0, t; }"
        : "=r"(a) : "l"(p));
    return a;
}

__device__ __forceinline__ uint32_t f2tf32(float f) {
    uint32_t r;
    asm("cvt.rna.tf32.f32 %0, %1;" : "=r"(r) : "f"(f));
    return r;
}

__device__ __forceinline__ uint32_t cvt_bits(uint32_t b) {
    uint32_t r;
    asm("cvt.rna.tf32.f32 %0, %1;" : "=r"(r) : "r"(b));
    return r;
}

__device__ __forceinline__ void sts_v4(uint32_t a, uint32_t r0, uint32_t r1,
                                       uint32_t r2, uint32_t r3) {
    asm volatile("st.shared.v4.b32 [%0], {%1, %2, %3, %4};"
                 :: "r"(a), "r"(r0), "r"(r1), "r"(r2), "r"(r3) : "memory");
}

__device__ __forceinline__ void cp_async16(uint32_t dst, const void* src) {
    asm volatile("cp.async.cg.shared.global [%0], [%1], 16;"
                 :: "r"(dst), "l"(src) : "memory");
}

__device__ __forceinline__ void cp_commit() {
    asm volatile("cp.async.commit_group;" ::: "memory");
}

__device__ __forceinline__ void cp_wait1() {
    asm volatile("cp.async.wait_group 1;" ::: "memory");
}

// ldmatrix x4: four 8x(8xb16) tiles; lane l supplies row (l&7) of tile (l>>3)
__device__ __forceinline__ void ldsm_x4(uint32_t* r, uint32_t addr) {
    asm volatile("ldmatrix.sync.aligned.m8n8.x4.shared.b16 {%0,%1,%2,%3}, [%4];"
                 : "=r"(r[0]), "=r"(r[1]), "=r"(r[2]), "=r"(r[3]) : "r"(addr));
}

// mma.sync m16n8k8 tf32: d += a * b  (fp32 accumulate)
__device__ __forceinline__ void mma_tf32(float& d0, float& d1, float& d2, float& d3,
                                         uint32_t a0, uint32_t a1, uint32_t a2, uint32_t a3,
                                         uint32_t b0, uint32_t b1) {
    asm volatile(
        "mma.sync.aligned.m16n8k8.row.col.f32.tf32.tf32.f32 "
        "{%0,%1,%2,%3}, {%4,%5,%6,%7}, {%8,%9}, {%0,%1,%2,%3};"
        : "+f"(d0), "+f"(d1), "+f"(d2), "+f"(d3)
        : "r"(a0), "r"(a1), "r"(a2), "r"(a3), "r"(b0), "r"(b1));
}

// ============================================================================
// Grouped GEMM:  C[e, :, :] = act( A[e] @ W[e] + bias )
//   A: [E, NTOK, K] row-major (K contiguous)   -> smem raw fp32 via cp.async
//   W: [E, K, N]    row-major (N contiguous)   -> smem tf32, transposed on store
//   C: [E, NTOK, N]
// Per CTA: 128x128 tile, 256 threads, 8 warps (2m x 4n), warp tile 64x32.
// Smem rows are 128B (32 floats) with XOR-16B swizzle: unit' = unit ^ (row&7).
// Fragments via ldmatrix.x4 (A cvt'd to tf32 post-load).
// ============================================================================
__global__ void __launch_bounds__(THREADS, 2)
grouped_gemm_tf32(const float* __restrict__ A, const float* __restrict__ W,
                  const float* __restrict__ bias, float* __restrict__ C,
                  int K, int N, int NT, int doGelu)
{
    extern __shared__ char smem[];
    const uint32_t sb = smem_u32(smem);
    const int tid  = threadIdx.x;
    const int lane = tid & 31;
    const int wid  = tid >> 5;

    // CTA tile coordinates
    const int bid = blockIdx.x;
    const int e   = bid / (MT * NT);
    const int rr  = bid % (MT * NT);
    const int mt  = rr / NT;
    const int nt  = rr % NT;

    const float* Ae = A + (size_t)e * NTOK * K + (size_t)mt * BM * K;
    const float* We = W + (size_t)e * K * N + (size_t)nt * BN;
    float*       Ce = C + (size_t)e * NTOK * N + (size_t)mt * BM * N + (size_t)nt * BN;

    // warp layout: 2 warps along M (64 rows each), 4 along N (32 cols each)
    const int mbase = (wid & 1) * 64;
    const int nbase = (wid >> 1) * 32;
    const int g  = lane >> 2;   // group id 0..7
    const int tg = lane & 3;    // thread-in-group 0..3

    // ldmatrix per-lane addressing (same mapping as R4, proven):
    const uint32_t swz    = lane & 7;
    const uint32_t a_usel = (lane >> 4) & 1;
    const uint32_t b_usel = (lane >> 3) & 1;
    const uint32_t a_rowo = (((lane >> 3) & 1) << 3) + swz;
    const uint32_t b_rowo = (((lane >> 4) & 1) << 3) + swz;

    // loader indices (256 threads)
    const int arow0 = tid >> 3;          // A: 8 threads/row, rows arow0 + 32*i (i<4)
    const int au    = tid & 7;           // 16B unit within 128B row
    const int bn_   = tid & 127;         // B: n index
    const int bkh   = (tid >> 7) * 16;   // B: k offset (0 or 16), 2 threads per n

    float acc[64];
    #pragma unroll
    for (int i = 0; i < 64; i++) acc[i] = 0.0f;

    float bpre[16];
    const int CH = K / BK;

    // ---------------- prologue: fill stages 0..STAGES-2 ----------------
    #pragma unroll
    for (int s = 0; s < STAGES - 1; s++) {
        const uint32_t sA = sb + s * STAGE_BYTES;
        const uint32_t sB = sA + A_BYTES;
        const int k0 = s * BK;
        // B: gmem -> reg -> tf32 -> smem [n][k] swizzled
        const float* wp = We + bn_ + (size_t)(k0 + bkh) * N;
        #pragma unroll
        for (int j = 0; j < 16; j++) bpre[j] = wp[(size_t)j * N];
        #pragma unroll
        for (int j = 0; j < 4; j++) {
            const uint32_t unit = (bkh >> 2) + j;
            sts_v4(sB + bn_ * 128 + ((unit ^ (bn_ & 7)) << 4),
                   f2tf32(bpre[4*j+0]), f2tf32(bpre[4*j+1]),
                   f2tf32(bpre[4*j+2]), f2tf32(bpre[4*j+3]));
        }
        // A: cp.async raw fp32, swizzled 16B units
        #pragma unroll
        for (int i = 0; i < 4; i++) {
            const int r = arow0 + 32 * i;
            cp_async16(sA + r * 128 + ((au ^ (r & 7)) << 4),
                       Ae + (size_t)r * K + k0 + au * 4);
        }
        cp_commit();
    }
    // prefetch B chunk STAGES-1 into regs
    {
        const float* wp = We + bn_ + (size_t)((STAGES - 1) * BK + bkh) * N;
        #pragma unroll
        for (int j = 0; j < 16; j++) bpre[j] = wp[(size_t)j * N];
    }

    // ---------------- main loop ----------------
    for (int c = 0; c < CH; c++) {
        cp_wait1();
        __syncthreads();

        const int cn = c + STAGES - 1;
        if (cn < CH) {
            const int s = cn % STAGES;
            const uint32_t sA = sb + s * STAGE_BYTES;
            const uint32_t sB = sA + A_BYTES;
            #pragma unroll
            for (int j = 0; j < 4; j++) {
                const uint32_t unit = (bkh >> 2) + j;
                sts_v4(sB + bn_ * 128 + ((unit ^ (bn_ & 7)) << 4),
                       f2tf32(bpre[4*j+0]), f2tf32(bpre[4*j+1]),
                       f2tf32(bpre[4*j+2]), f2tf32(bpre[4*j+3]));
            }
            const int k0 = cn * BK;
            #pragma unroll
            for (int i = 0; i < 4; i++) {
                const int r = arow0 + 32 * i;
                cp_async16(sA + r * 128 + ((au ^ (r & 7)) << 4),
                           Ae + (size_t)r * K + k0 + au * 4);
            }
        }
        cp_commit();
        if (cn + 1 < CH) {
            const float* wp = We + bn_ + (size_t)((cn + 1) * BK + bkh) * N;
            #pragma unroll
            for (int j = 0; j < 16; j++) bpre[j] = wp[(size_t)j * N];
        }

        // ---- compute this stage ----
        const int sc = c % STAGES;
        const uint32_t sA = sb + sc * STAGE_BYTES;
        const uint32_t sB = sA + A_BYTES;
        const uint32_t aBase = sA + (mbase + a_rowo) * 128;
        const uint32_t bBase = sB + (nbase + b_rowo) * 128;

        #pragma unroll
        for (int ks = 0; ks < 4; ks++) {
            const uint32_t xa = (((uint32_t)(2 * ks) + a_usel) ^ swz) << 4;
            const uint32_t xb = (((uint32_t)(2 * ks) + b_usel) ^ swz) << 4;

            uint32_t af[16];
            #pragma unroll
            for (int m2 = 0; m2 < 4; m2++)
                ldsm_x4(&af[4 * m2], aBase + m2 * 2048 + xa);   // 16 rows * 128B

            uint32_t bf[8];
            #pragma unroll
            for (int p = 0; p < 2; p++)
                ldsm_x4(&bf[4 * p], bBase + p * 2048 + xb);

            #pragma unroll
            for (int i = 0; i < 16; i++) af[i] = cvt_bits(af[i]);  // raw fp32 -> tf32

            #pragma unroll
            for (int m2 = 0; m2 < 4; m2++) {
                #pragma unroll
                for (int n2 = 0; n2 < 4; n2++) {
                    // bf[4p + 2q + {0,1}] = {b0,b1} for n2 = 2p+q
                    const int p = n2 >> 1, q = n2 & 1;
                    float* d = &acc[(m2 * 4 + n2) * 4];
                    mma_tf32(d[0], d[1], d[2], d[3],
                             af[4*m2+0], af[4*m2+1], af[4*m2+2], af[4*m2+3],
                             bf[4*p + 2*q], bf[4*p + 2*q + 1]);
                }
            }
        }
    }

    // ---------------- epilogue: bias + (optional) exact GELU ----------------
    const int ncol0 = nt * BN;
    #pragma unroll
    for (int m2 = 0; m2 < 4; m2++) {
        const int r0 = mbase + m2 * 16 + g;
        #pragma unroll
        for (int n2 = 0; n2 < 4; n2++) {
            const int col = nbase + n2 * 8 + tg * 2;
            const float bv0 = __ldg(&bias[ncol0 + col]);
            const float bv1 = __ldg(&bias[ncol0 + col + 1]);
            float* d = &acc[(m2 * 4 + n2) * 4];
            float v0 = d[0] + bv0, v1 = d[1] + bv1;
            float v2 = d[2] + bv0, v3 = d[3] + bv1;
            if (doGelu) {
                v0 = 0.5f * v0 * (1.0f + erff(v0 * 0.70710678118654752440f));
                v1 = 0.5f * v1 * (1.0f + erff(v1 * 0.70710678118654752440f));
                v2 = 0.5f * v2 * (1.0f + erff(v2 * 0.70710678118654752440f));
                v3 = 0.5f * v3 * (1.0f + erff(v3 * 0.70710678118654752440f));
            }
            *reinterpret_cast<float2*>(Ce + (size_t)r0 * N + col)       = make_float2(v0, v1);
            *reinterpret_cast<float2*>(Ce + (size_t)(r0 + 8) * N + col) = make_float2(v2, v3);
        }
    }
}

// ============================================================================
// Launch
// ============================================================================
extern "C" void kernel_launch(void* const* d_in, const int* in_sizes, int n_in,
                              void* d_out, int out_size)
{
    const float* x  = (const float*)d_in[0];
    const float* w1 = (const float*)d_in[1];
    const float* w2 = (const float*)d_in[2];
    const float* b1 = (const float*)d_in[3];
    const float* b2 = (const float*)d_in[4];
    float* out = (float*)d_out;

    float* hidden = nullptr;
    cudaGetSymbolAddress((void**)&hidden, g_hidden);

    cudaFuncSetAttribute(grouped_gemm_tf32,
                         cudaFuncAttributeMaxDynamicSharedMemorySize, SMEM_TOTAL);

    // GEMM1 + GELU: [E,2048,1024] @ [E,1024,4096] -> hidden
    {
        const int NT = HDIM / BN;  // 32
        grouped_gemm_tf32<<<E_ * MT * NT, THREADS, SMEM_TOTAL>>>(
            x, w1, b1, hidden, DDIM, HDIM, NT, 1);
    }
    // GEMM2: hidden @ [E,4096,1024] -> out
    {
        const int NT = DDIM / BN;  // 8
        grouped_gemm_tf32<<<E_ * MT * NT, THREADS, SMEM_TOTAL>>>(
            hidden, w2, b2, out, HDIM, DDIM, NT, 0);
    }
}

// round 7
// speedup vs baseline: 1.1931x; 1.1931x over previous
#include <cuda_runtime.h>
#include <cstdint>

// ============================================================================
// Problem constants
// ============================================================================
static constexpr int E_   = 16;
static constexpr int NTOK = 2048;
static constexpr int DDIM = 1024;
static constexpr int HDIM = 4096;

// Tile config: 128x128 CTA tile, 128 threads (4 warps, 2x2 of 64x64 warp tiles)
static constexpr int BM = 128;
static constexpr int BN = 128;
static constexpr int BK = 32;              // 32 fp32 = 128 B rows
static constexpr int STAGES = 3;
static constexpr int THREADS = 128;
static constexpr int MT = NTOK / BM;       // 16 M-tiles

static constexpr int A_BYTES     = BM * 128;             // 16 KB / stage
static constexpr int B_BYTES     = BN * 128;             // 16 KB / stage
static constexpr int STAGE_BYTES = A_BYTES + B_BYTES;    // 32 KB
static constexpr int SMEM_TOTAL  = STAGES * STAGE_BYTES; // 96 KB  (2 CTAs/SM)

// Hidden activations (no cudaMalloc allowed -> device global)
__device__ float g_hidden[(size_t)E_ * NTOK * HDIM];

// ============================================================================
// PTX helpers (plain sm_80+ features only — ptxas target is sm_103 WITHOUT 'a')
// ============================================================================
__device__ __forceinline__ uint32_t smem_u32(const void* p) {
    uint32_t a;
    asm("{ .reg .u64 t; cvta.to.shared.u64 t, %1; cvt.u32.u64 %0, t; }"
        : "=r"(a) : "l"(p));
    return a;
}

__device__ __forceinline__ uint32_t f2tf32(float f) {
    uint32_t r;
    asm("cvt.rna.tf32.f32 %0, %1;" : "=r"(r) : "f"(f));
    return r;
}

__device__ __forceinline__ uint32_t cvt_bits(uint32_t b) {
    uint32_t r;
    asm("cvt.rna.tf32.f32 %0, %1;" : "=r"(r) : "r"(b));
    return r;
}

__device__ __forceinline__ void sts_v4(uint32_t a, uint32_t r0, uint32_t r1,
                                       uint32_t r2, uint32_t r3) {
    asm volatile("st.shared.v4.b32 [%0], {%1, %2, %3, %4};"
                 :: "r"(a), "r"(r0), "r"(r1), "r"(r2), "r"(r3) : "memory");
}

__device__ __forceinline__ void cp_async16(uint32_t dst, const void* src) {
    asm volatile("cp.async.cg.shared.global [%0], [%1], 16;"
                 :: "r"(dst), "l"(src) : "memory");
}

__device__ __forceinline__ void cp_commit() {
    asm volatile("cp.async.commit_group;" ::: "memory");
}

__device__ __forceinline__ void cp_wait1() {
    asm volatile("cp.async.wait_group 1;" ::: "memory");
}

// ldmatrix x4: four 8x(8xb16) tiles; lane l supplies row (l&7) of tile (l>>3)
__device__ __forceinline__ void ldsm_x4(uint32_t* r, uint32_t addr) {
    asm volatile("ldmatrix.sync.aligned.m8n8.x4.shared.b16 {%0,%1,%2,%3}, [%4];"
                 : "=r"(r[0]), "=r"(r[1]), "=r"(r[2]), "=r"(r[3]) : "r"(addr));
}

// mma.sync m16n8k8 tf32: d += a * b  (fp32 accumulate)
__device__ __forceinline__ void mma_tf32(float& d0, float& d1, float& d2, float& d3,
                                         uint32_t a0, uint32_t a1, uint32_t a2, uint32_t a3,
                                         uint32_t b0, uint32_t b1) {
    asm volatile(
        "mma.sync.aligned.m16n8k8.row.col.f32.tf32.tf32.f32 "
        "{%0,%1,%2,%3}, {%4,%5,%6,%7}, {%8,%9}, {%0,%1,%2,%3};"
        : "+f"(d0), "+f"(d1), "+f"(d2), "+f"(d3)
        : "r"(a0), "r"(a1), "r"(a2), "r"(a3), "r"(b0), "r"(b1));
}

// ============================================================================
// Grouped GEMM (compile-time K/N):  C[e] = act( A[e] @ W[e] + bias )
//   A: [E, NTOK, K] row-major -> smem raw fp32 via cp.async
//   W: [E, K, N]    row-major -> smem tf32, transposed on store
// Per CTA: 128x128 tile, 4 warps (2m x 2n), warp tile 64x64.
// Smem rows 128B, XOR-16B swizzle: unit' = unit ^ (row&7).
// All global strides are compile-time -> LDG/STG [reg + imm].
// ============================================================================
template <int K, int N, int NT, int GELU>
__global__ void __launch_bounds__(THREADS, 2)
grouped_gemm_tf32(const float* __restrict__ A, const float* __restrict__ W,
                  const float* __restrict__ bias, float* __restrict__ C)
{
    extern __shared__ char smem[];
    const uint32_t sb = smem_u32(smem);
    const int tid  = threadIdx.x;
    const int lane = tid & 31;
    const int wid  = tid >> 5;

    // CTA tile coordinates
    const int bid = blockIdx.x;
    const int e   = bid / (MT * NT);
    const int rr  = bid % (MT * NT);
    const int mt  = rr / NT;
    const int nt  = rr % NT;

    const float* Ae = A + (size_t)e * NTOK * K + (size_t)mt * BM * K;
    const float* We = W + (size_t)e * K * N + (size_t)nt * BN;
    float*       Ce = C + (size_t)e * NTOK * N + (size_t)mt * BM * N + (size_t)nt * BN;

    // warp layout: 2 warps along M (64 rows each), 2 along N (64 cols each)
    const int mbase = (wid & 1) * 64;
    const int nbase = (wid >> 1) * 64;
    const int g  = lane >> 2;   // group id 0..7
    const int tg = lane & 3;    // thread-in-group 0..3

    // ldmatrix per-lane addressing (proven in R4):
    const uint32_t swz    = lane & 7;
    const uint32_t a_usel = (lane >> 4) & 1;
    const uint32_t b_usel = (lane >> 3) & 1;
    const uint32_t a_rowo = (((lane >> 3) & 1) << 3) + swz;
    const uint32_t b_rowo = (((lane >> 4) & 1) << 3) + swz;

    // loader indices
    const int arow0 = tid >> 3;          // A: 8 threads/row, rows arow0 + 16*i
    const int au    = tid & 7;           // 16B unit within 128B row
    const int bn_   = tid;               // B: one thread per n-row (128 rows)

    // Running source pointers (advance by compile-time strides)
    const float* aP = Ae + (size_t)arow0 * K + au * 4;   // chunk c: aP + c*BK
    const float* wP = We + bn_;                          // chunk c: wP + c*BK*N (+ j*N imm)

    // Precomputed smem store addresses (swizzle folded once)
    const uint32_t aSts = sb + arow0 * 128 + (((uint32_t)au ^ (arow0 & 7)) << 4);
    uint32_t bSts[8];
    #pragma unroll
    for (int j = 0; j < 8; j++)
        bSts[j] = sb + A_BYTES + bn_ * 128 + (((uint32_t)j ^ (bn_ & 7)) << 4);

    float acc[128];
    #pragma unroll
    for (int i = 0; i < 128; i++) acc[i] = 0.0f;

    float bpre[32];
    constexpr int CH = K / BK;

    // ---------------- prologue: fill stages 0..STAGES-2 ----------------
    #pragma unroll
    for (int s = 0; s < STAGES - 1; s++) {
        const uint32_t stg = s * STAGE_BYTES;
        // B: gmem -> reg -> tf32 -> smem [n][k] swizzled (immediate offsets)
        const float* wp = wP + (size_t)s * BK * N;
        #pragma unroll
        for (int j = 0; j < 32; j++) bpre[j] = wp[(size_t)j * N];
        #pragma unroll
        for (int j = 0; j < 8; j++) {
            sts_v4(bSts[j] + stg,
                   f2tf32(bpre[4*j+0]), f2tf32(bpre[4*j+1]),
                   f2tf32(bpre[4*j+2]), f2tf32(bpre[4*j+3]));
        }
        // A: cp.async raw fp32, swizzled 16B units
        #pragma unroll
        for (int i = 0; i < 8; i++) {
            cp_async16(aSts + stg + i * 2048,          // 16 rows * 128B
                       aP + s * BK + (size_t)i * 16 * K);
        }
        cp_commit();
    }
    // prefetch B chunk STAGES-1 into regs
    {
        const float* wp = wP + (size_t)(STAGES - 1) * BK * N;
        #pragma unroll
        for (int j = 0; j < 32; j++) bpre[j] = wp[(size_t)j * N];
    }
    const float* aRun = aP + STAGES * BK;                      // next A chunk to issue
    const float* wRun = wP + (size_t)STAGES * BK * N;          // next B chunk to prefetch

    // ---------------- main loop ----------------
    #pragma unroll 1
    for (int c = 0; c < CH; c++) {
        cp_wait1();
        __syncthreads();

        const int cn = c + STAGES - 1;
        if (cn < CH) {
            const uint32_t stg = (cn % STAGES) * STAGE_BYTES;
            #pragma unroll
            for (int j = 0; j < 8; j++) {
                sts_v4(bSts[j] + stg,
                       f2tf32(bpre[4*j+0]), f2tf32(bpre[4*j+1]),
                       f2tf32(bpre[4*j+2]), f2tf32(bpre[4*j+3]));
            }
            const float* ap = aRun - BK;   // chunk cn = (c+2): aP + cn*BK
            #pragma unroll
            for (int i = 0; i < 8; i++) {
                cp_async16(aSts + stg + i * 2048, ap + (size_t)i * 16 * K);
            }
        }
        cp_commit();
        if (cn + 1 < CH) {
            #pragma unroll
            for (int j = 0; j < 32; j++) bpre[j] = wRun[(size_t)j * N];
        }
        aRun += BK;
        wRun += (size_t)BK * N;

        // ---- compute this stage ----
        const uint32_t stg = (c % STAGES) * STAGE_BYTES;
        const uint32_t aBase = sb + stg + (mbase + a_rowo) * 128;
        const uint32_t bBase = sb + stg + A_BYTES + (nbase + b_rowo) * 128;

        #pragma unroll
        for (int ks = 0; ks < 4; ks++) {
            const uint32_t xa = (((uint32_t)(2 * ks) + a_usel) ^ swz) << 4;
            const uint32_t xb = (((uint32_t)(2 * ks) + b_usel) ^ swz) << 4;

            uint32_t af[16];
            #pragma unroll
            for (int m2 = 0; m2 < 4; m2++)
                ldsm_x4(&af[4 * m2], aBase + m2 * 2048 + xa);   // 16 rows * 128B

            uint32_t bf[16];
            #pragma unroll
            for (int p = 0; p < 4; p++)
                ldsm_x4(&bf[4 * p], bBase + p * 2048 + xb);

            #pragma unroll
            for (int i = 0; i < 16; i++) af[i] = cvt_bits(af[i]);  // raw fp32 -> tf32

            #pragma unroll
            for (int m2 = 0; m2 < 4; m2++) {
                #pragma unroll
                for (int n2 = 0; n2 < 8; n2++) {
                    const int p = n2 >> 1, q = n2 & 1;
                    float* d = &acc[(m2 * 8 + n2) * 4];
                    mma_tf32(d[0], d[1], d[2], d[3],
                             af[4*m2+0], af[4*m2+1], af[4*m2+2], af[4*m2+3],
                             bf[4*p + 2*q], bf[4*p + 2*q + 1]);
                }
            }
        }
    }

    // ---------------- epilogue: bias + (optional) exact GELU ----------------
    const float* bptr = bias + nt * BN;
    #pragma unroll
    for (int m2 = 0; m2 < 4; m2++) {
        const int r0 = mbase + m2 * 16 + g;
        float* crow = Ce + (size_t)r0 * N;
        #pragma unroll
        for (int n2 = 0; n2 < 8; n2++) {
            const int col = nbase + n2 * 8 + tg * 2;
            const float bv0 = __ldg(bptr + col);
            const float bv1 = __ldg(bptr + col + 1);
            float* d = &acc[(m2 * 8 + n2) * 4];
            float v0 = d[0] + bv0, v1 = d[1] + bv1;
            float v2 = d[2] + bv0, v3 = d[3] + bv1;
            if (GELU) {
                v0 = 0.5f * v0 * (1.0f + erff(v0 * 0.70710678118654752440f));
                v1 = 0.5f * v1 * (1.0f + erff(v1 * 0.70710678118654752440f));
                v2 = 0.5f * v2 * (1.0f + erff(v2 * 0.70710678118654752440f));
                v3 = 0.5f * v3 * (1.0f + erff(v3 * 0.70710678118654752440f));
            }
            *reinterpret_cast<float2*>(crow + col)           = make_float2(v0, v1);
            *reinterpret_cast<float2*>(crow + 8 * N + col)   = make_float2(v2, v3);
        }
    }
}

// ============================================================================
// Launch
// ============================================================================
extern "C" void kernel_launch(void* const* d_in, const int* in_sizes, int n_in,
                              void* d_out, int out_size)
{
    const float* x  = (const float*)d_in[0];
    const float* w1 = (const float*)d_in[1];
    const float* w2 = (const float*)d_in[2];
    const float* b1 = (const float*)d_in[3];
    const float* b2 = (const float*)d_in[4];
    float* out = (float*)d_out;

    float* hidden = nullptr;
    cudaGetSymbolAddress((void**)&hidden, g_hidden);

    cudaFuncSetAttribute(grouped_gemm_tf32<DDIM, HDIM, HDIM / BN, 1>,
                         cudaFuncAttributeMaxDynamicSharedMemorySize, SMEM_TOTAL);
    cudaFuncSetAttribute(grouped_gemm_tf32<HDIM, DDIM, DDIM / BN, 0>,
                         cudaFuncAttributeMaxDynamicSharedMemorySize, SMEM_TOTAL);

    // GEMM1 + GELU: [E,2048,1024] @ [E,1024,4096] -> hidden
    grouped_gemm_tf32<DDIM, HDIM, HDIM / BN, 1>
        <<<E_ * MT * (HDIM / BN), THREADS, SMEM_TOTAL>>>(x, w1, b1, hidden);

    // GEMM2: hidden @ [E,4096,1024] -> out
    grouped_gemm_tf32<HDIM, DDIM, DDIM / BN, 0>
        <<<E_ * MT * (DDIM / BN), THREADS, SMEM_TOTAL>>>(hidden, w2, b2, out);
}

// round 9
// speedup vs baseline: 1.1964x; 1.0028x over previous
#include <cuda_runtime.h>
#include <cstdint>

// ============================================================================
// Problem constants
// ============================================================================
static constexpr int E_   = 16;
static constexpr int NTOK = 2048;
static constexpr int DDIM = 1024;
static constexpr int HDIM = 4096;

// Tile config: 128x128 CTA tile, 128 threads (4 warps, 2x2 of 64x64 warp tiles)
static constexpr int BM = 128;
static constexpr int BN = 128;
static constexpr int BK = 32;              // 32 fp32 = 128 B rows
static constexpr int STAGES = 3;
static constexpr int THREADS = 128;
static constexpr int MT = NTOK / BM;       // 16 M-tiles

static constexpr int A_BYTES     = BM * 128;             // 16 KB / stage
static constexpr int B_BYTES     = BN * 128;             // 16 KB / stage
static constexpr int STAGE_BYTES = A_BYTES + B_BYTES;    // 32 KB
static constexpr int SMEM_TOTAL  = STAGES * STAGE_BYTES; // 96 KB  (2 CTAs/SM)

// Hidden activations (no cudaMalloc allowed -> device global)
__device__ float g_hidden[(size_t)E_ * NTOK * HDIM];

// ============================================================================
// PTX helpers (plain sm_80+ features only — ptxas target is sm_103 WITHOUT 'a')
// ============================================================================
__device__ __forceinline__ uint32_t smem_u32(const void* p) {
    uint32_t a;
    asm("{ .reg .u64 t; cvta.to.shared.u64 t, %1; cvt.u32.u64 %0, t; }"
        : "=r"(a) : "l"(p));
    return a;
}

__device__ __forceinline__ uint32_t f2tf32(float f) {
    uint32_t r;
    asm("cvt.rna.tf32.f32 %0, %1;" : "=r"(r) : "f"(f));
    return r;
}

__device__ __forceinline__ uint32_t cvt_bits(uint32_t b) {
    uint32_t r;
    asm("cvt.rna.tf32.f32 %0, %1;" : "=r"(r) : "r"(b));
    return r;
}

__device__ __forceinline__ void sts_v4(uint32_t a, uint32_t r0, uint32_t r1,
                                       uint32_t r2, uint32_t r3) {
    asm volatile("st.shared.v4.b32 [%0], {%1, %2, %3, %4};"
                 :: "r"(a), "r"(r0), "r"(r1), "r"(r2), "r"(r3) : "memory");
}

__device__ __forceinline__ void cp_async16(uint32_t dst, const void* src) {
    asm volatile("cp.async.cg.shared.global [%0], [%1], 16;"
                 :: "r"(dst), "l"(src) : "memory");
}

__device__ __forceinline__ void cp_commit() {
    asm volatile("cp.async.commit_group;" ::: "memory");
}

__device__ __forceinline__ void cp_wait1() {
    asm volatile("cp.async.wait_group 1;" ::: "memory");
}

// ldmatrix x4: four 8x(8xb16) tiles; lane l supplies row (l&7) of tile (l>>3)
__device__ __forceinline__ void ldsm_x4(uint32_t* r, uint32_t addr) {
    asm volatile("ldmatrix.sync.aligned.m8n8.x4.shared.b16 {%0,%1,%2,%3}, [%4];"
                 : "=r"(r[0]), "=r"(r[1]), "=r"(r[2]), "=r"(r[3]) : "r"(addr));
}

// mma.sync m16n8k8 tf32: d += a * b  (fp32 accumulate)
__device__ __forceinline__ void mma_tf32(float& d0, float& d1, float& d2, float& d3,
                                         uint32_t a0, uint32_t a1, uint32_t a2, uint32_t a3,
                                         uint32_t b0, uint32_t b1) {
    asm volatile(
        "mma.sync.aligned.m16n8k8.row.col.f32.tf32.tf32.f32 "
        "{%0,%1,%2,%3}, {%4,%5,%6,%7}, {%8,%9}, {%0,%1,%2,%3};"
        : "+f"(d0), "+f"(d1), "+f"(d2), "+f"(d3)
        : "r"(a0), "r"(a1), "r"(a2), "r"(a3), "r"(b0), "r"(b1));
}

// ============================================================================
// Grouped GEMM (compile-time K/N):  C[e] = act( A[e] @ W[e] + bias )
//   A: [E, NTOK, K] row-major -> smem raw fp32 via cp.async
//   W: [E, K, N]    row-major -> smem tf32, transposed on store
// Per CTA: 128x128 tile, 4 warps (2m x 2n), warp tile 64x64.
// Smem rows 128B, XOR-16B swizzle: unit' = unit ^ (row&7).
// Compile-time global strides; fragments double-buffered across ks-steps.
// ============================================================================
template <int K, int N, int NT, int GELU>
__global__ void __launch_bounds__(THREADS, 2)
grouped_gemm_tf32(const float* __restrict__ A, const float* __restrict__ W,
                  const float* __restrict__ bias, float* __restrict__ C)
{
    extern __shared__ char smem[];
    const uint32_t sb = smem_u32(smem);
    const int tid  = threadIdx.x;
    const int lane = tid & 31;
    const int wid  = tid >> 5;

    // CTA tile coordinates
    const int bid = blockIdx.x;
    const int e   = bid / (MT * NT);
    const int rr  = bid % (MT * NT);
    const int mt  = rr / NT;
    const int nt  = rr % NT;

    const float* Ae = A + (size_t)e * NTOK * K + (size_t)mt * BM * K;
    const float* We = W + (size_t)e * K * N + (size_t)nt * BN;
    float*       Ce = C + (size_t)e * NTOK * N + (size_t)mt * BM * N + (size_t)nt * BN;

    // warp layout: 2 warps along M (64 rows each), 2 along N (64 cols each)
    const int mbase = (wid & 1) * 64;
    const int nbase = (wid >> 1) * 64;
    const int g  = lane >> 2;   // group id 0..7
    const int tg = lane & 3;    // thread-in-group 0..3

    // ldmatrix per-lane addressing (proven in R4):
    const uint32_t swz    = lane & 7;
    const uint32_t a_usel = (lane >> 4) & 1;
    const uint32_t b_usel = (lane >> 3) & 1;
    const uint32_t a_rowo = (((lane >> 3) & 1) << 3) + swz;
    const uint32_t b_rowo = (((lane >> 4) & 1) << 3) + swz;

    // loader indices
    const int arow0 = tid >> 3;          // A: 8 threads/row, rows arow0 + 16*i
    const int au    = tid & 7;           // 16B unit within 128B row
    const int bn_   = tid;               // B: one thread per n-row (128 rows)

    // Running source pointers (advance by compile-time strides)
    const float* aP = Ae + (size_t)arow0 * K + au * 4;   // chunk c: aP + c*BK
    const float* wP = We + bn_;                          // chunk c: wP + c*BK*N (+ j*N imm)

    // Precomputed smem store addresses (swizzle folded once)
    const uint32_t aSts = sb + arow0 * 128 + (((uint32_t)au ^ (arow0 & 7)) << 4);
    uint32_t bSts[8];
    #pragma unroll
    for (int j = 0; j < 8; j++)
        bSts[j] = sb + A_BYTES + bn_ * 128 + (((uint32_t)j ^ (bn_ & 7)) << 4);

    float acc[128];
    #pragma unroll
    for (int i = 0; i < 128; i++) acc[i] = 0.0f;

    float bpre[32];
    constexpr int CH = K / BK;

    // ---------------- prologue: fill stages 0..STAGES-2 ----------------
    #pragma unroll
    for (int s = 0; s < STAGES - 1; s++) {
        const uint32_t stg = s * STAGE_BYTES;
        // B: gmem -> reg -> tf32 -> smem [n][k] swizzled (immediate offsets)
        const float* wp = wP + (size_t)s * BK * N;
        #pragma unroll
        for (int j = 0; j < 32; j++) bpre[j] = wp[(size_t)j * N];
        #pragma unroll
        for (int j = 0; j < 8; j++) {
            sts_v4(bSts[j] + stg,
                   f2tf32(bpre[4*j+0]), f2tf32(bpre[4*j+1]),
                   f2tf32(bpre[4*j+2]), f2tf32(bpre[4*j+3]));
        }
        // A: cp.async raw fp32, swizzled 16B units
        #pragma unroll
        for (int i = 0; i < 8; i++) {
            cp_async16(aSts + stg + i * 2048,          // 16 rows * 128B
                       aP + s * BK + (size_t)i * 16 * K);
        }
        cp_commit();
    }
    // prefetch B chunk STAGES-1 into regs
    {
        const float* wp = wP + (size_t)(STAGES - 1) * BK * N;
        #pragma unroll
        for (int j = 0; j < 32; j++) bpre[j] = wp[(size_t)j * N];
    }
    const float* aRun = aP + STAGES * BK;                      // next A chunk to issue
    const float* wRun = wP + (size_t)STAGES * BK * N;          // next B chunk to prefetch

    // ---------------- main loop ----------------
    #pragma unroll 1
    for (int c = 0; c < CH; c++) {
        cp_wait1();
        __syncthreads();

        // compute-stage bases (needed for early fragment preload)
        const uint32_t stg   = (c % STAGES) * STAGE_BYTES;
        const uint32_t aBase = sb + stg + (mbase + a_rowo) * 128;
        const uint32_t bBase = sb + stg + A_BYTES + (nbase + b_rowo) * 128;

        uint32_t af[2][16], bf[2][16];
        // ---- preload ks=0 fragments; latency hides behind loader block ----
        {
            const uint32_t xa = ((0 + a_usel) ^ swz) << 4;
            const uint32_t xb = ((0 + b_usel) ^ swz) << 4;
            #pragma unroll
            for (int m2 = 0; m2 < 4; m2++)
                ldsm_x4(&af[0][4 * m2], aBase + m2 * 2048 + xa);
            #pragma unroll
            for (int p = 0; p < 4; p++)
                ldsm_x4(&bf[0][4 * p], bBase + p * 2048 + xb);
        }

        // ---- loader: stage chunk cn = c + STAGES - 1 ----
        const int cn = c + STAGES - 1;
        if (cn < CH) {
            const uint32_t lstg = (cn % STAGES) * STAGE_BYTES;
            #pragma unroll
            for (int j = 0; j < 8; j++) {
                sts_v4(bSts[j] + lstg,
                       f2tf32(bpre[4*j+0]), f2tf32(bpre[4*j+1]),
                       f2tf32(bpre[4*j+2]), f2tf32(bpre[4*j+3]));
            }
            const float* ap = aRun - BK;   // chunk cn: aP + cn*BK
            #pragma unroll
            for (int i = 0; i < 8; i++) {
                cp_async16(aSts + lstg + i * 2048, ap + (size_t)i * 16 * K);
            }
        }
        cp_commit();
        if (cn + 1 < CH) {
            #pragma unroll
            for (int j = 0; j < 32; j++) bpre[j] = wRun[(size_t)j * N];
        }
        aRun += BK;
        wRun += (size_t)BK * N;

        // ---- compute: double-buffered ks pipeline ----
        #pragma unroll
        for (int ks = 0; ks < 4; ks++) {
            const int cur = ks & 1;
            const int nxt = cur ^ 1;
            if (ks < 3) {
                const uint32_t xa = (((uint32_t)(2 * (ks + 1)) + a_usel) ^ swz) << 4;
                const uint32_t xb = (((uint32_t)(2 * (ks + 1)) + b_usel) ^ swz) << 4;
                #pragma unroll
                for (int m2 = 0; m2 < 4; m2++)
                    ldsm_x4(&af[nxt][4 * m2], aBase + m2 * 2048 + xa);
                #pragma unroll
                for (int p = 0; p < 4; p++)
                    ldsm_x4(&bf[nxt][4 * p], bBase + p * 2048 + xb);
            }

            #pragma unroll
            for (int i = 0; i < 16; i++) af[cur][i] = cvt_bits(af[cur][i]);

            #pragma unroll
            for (int m2 = 0; m2 < 4; m2++) {
                #pragma unroll
                for (int n2 = 0; n2 < 8; n2++) {
                    const int p = n2 >> 1, q = n2 & 1;
                    float* d = &acc[(m2 * 8 + n2) * 4];
                    mma_tf32(d[0], d[1], d[2], d[3],
                             af[cur][4*m2+0], af[cur][4*m2+1],
                             af[cur][4*m2+2], af[cur][4*m2+3],
                             bf[cur][4*p + 2*q], bf[cur][4*p + 2*q + 1]);
                }
            }
        }
    }

    // ---------------- epilogue: bias + (optional) exact GELU ----------------
    const float* bptr = bias + nt * BN;
    #pragma unroll
    for (int m2 = 0; m2 < 4; m2++) {
        const int r0 = mbase + m2 * 16 + g;
        float* crow = Ce + (size_t)r0 * N;
        #pragma unroll
        for (int n2 = 0; n2 < 8; n2++) {
            const int col = nbase + n2 * 8 + tg * 2;
            const float bv0 = __ldg(bptr + col);
            const float bv1 = __ldg(bptr + col + 1);
            float* d = &acc[(m2 * 8 + n2) * 4];
            float v0 = d[0] + bv0, v1 = d[1] + bv1;
            float v2 = d[2] + bv0, v3 = d[3] + bv1;
            if (GELU) {
                v0 = 0.5f * v0 * (1.0f + erff(v0 * 0.70710678118654752440f));
                v1 = 0.5f * v1 * (1.0f + erff(v1 * 0.70710678118654752440f));
                v2 = 0.5f * v2 * (1.0f + erff(v2 * 0.70710678118654752440f));
                v3 = 0.5f * v3 * (1.0f + erff(v3 * 0.70710678118654752440f));
            }
            *reinterpret_cast<float2*>(crow + col)           = make_float2(v0, v1);
            *reinterpret_cast<float2*>(crow + 8 * N + col)   = make_float2(v2, v3);
        }
    }
}

// ============================================================================
// Launch
// ============================================================================
extern "C" void kernel_launch(void* const* d_in, const int* in_sizes, int n_in,
                              void* d_out, int out_size)
{
    const float* x  = (const float*)d_in[0];
    const float* w1 = (const float*)d_in[1];
    const float* w2 = (const float*)d_in[2];
    const float* b1 = (const float*)d_in[3];
    const float* b2 = (const float*)d_in[4];
    float* out = (float*)d_out;

    float* hidden = nullptr;
    cudaGetSymbolAddress((void**)&hidden, g_hidden);

    cudaFuncSetAttribute(grouped_gemm_tf32<DDIM, HDIM, HDIM / BN, 1>,
                         cudaFuncAttributeMaxDynamicSharedMemorySize, SMEM_TOTAL);
    cudaFuncSetAttribute(grouped_gemm_tf32<HDIM, DDIM, DDIM / BN, 0>,
                         cudaFuncAttributeMaxDynamicSharedMemorySize, SMEM_TOTAL);

    // GEMM1 + GELU: [E,2048,1024] @ [E,1024,4096] -> hidden
    grouped_gemm_tf32<DDIM, HDIM, HDIM / BN, 1>
        <<<E_ * MT * (HDIM / BN), THREADS, SMEM_TOTAL>>>(x, w1, b1, hidden);

    // GEMM2: hidden @ [E,4096,1024] -> out
    grouped_gemm_tf32<HDIM, DDIM, DDIM / BN, 0>
        <<<E_ * MT * (DDIM / BN), THREADS, SMEM_TOTAL>>>(hidden, w2, b2, out);
}

// round 14
// speedup vs baseline: 1.4652x; 1.2247x over previous
#include <cuda_runtime.h>
#include <cstdint>

// ============================================================================
// Problem constants
// ============================================================================
static constexpr int E_   = 16;
static constexpr int NTOK = 2048;
static constexpr int DDIM = 1024;
static constexpr int HDIM = 4096;

// Tile config: 128x128 CTA tile, 128 threads (4 warps, 2x2 of 64x64 warp tiles)
static constexpr int BM = 128;
static constexpr int BN = 128;
static constexpr int BK = 32;              // 32 fp32 = 128 B rows
static constexpr int STAGES = 3;
static constexpr int THREADS = 128;
static constexpr int MT = NTOK / BM;       // 16 M-tiles

static constexpr int A_BYTES     = BM * 128;             // 16 KB / stage
static constexpr int B_BYTES     = BN * 128;             // 16 KB / stage
static constexpr int STAGE_BYTES = A_BYTES + B_BYTES;    // 32 KB
static constexpr int SMEM_TOTAL  = STAGES * STAGE_BYTES; // 96 KB  (2 CTAs/SM)

// Scratch (no cudaMalloc allowed -> device globals)
__device__ float g_hidden[(size_t)E_ * NTOK * HDIM];   // tf32-rounded activations
__device__ float g_xs[(size_t)E_ * NTOK * DDIM];       // tf32-rounded x
__device__ float g_w1t[(size_t)E_ * HDIM * DDIM];      // w1 transposed [e][H][D], tf32
__device__ float g_w2t[(size_t)E_ * DDIM * HDIM];      // w2 transposed [e][D][H], tf32

// ============================================================================
// PTX helpers (plain sm_80+ features only — ptxas target is sm_103 WITHOUT 'a')
// ============================================================================
__device__ __forceinline__ uint32_t smem_u32(const void* p) {
    uint32_t a;
    asm("{ .reg .u64 t; cvta.to.shared.u64 t, %1; cvt.u32.u64 %0, t; }"
        : "=r"(a) : "l"(p));
    return a;
}

__device__ __forceinline__ uint32_t f2tf32(float f) {
    uint32_t r;
    asm("cvt.rna.tf32.f32 %0, %1;" : "=r"(r) : "f"(f));
    return r;
}

__device__ __forceinline__ void cp_async16(uint32_t dst, const void* src) {
    asm volatile("cp.async.cg.shared.global [%0], [%1], 16;"
                 :: "r"(dst), "l"(src) : "memory");
}

__device__ __forceinline__ void cp_commit() {
    asm volatile("cp.async.commit_group;" ::: "memory");
}

__device__ __forceinline__ void cp_wait1() {
    asm volatile("cp.async.wait_group 1;" ::: "memory");
}

// ldmatrix x4: four 8x(8xb16) tiles; lane l supplies row (l&7) of tile (l>>3)
__device__ __forceinline__ void ldsm_x4(uint32_t* r, uint32_t addr) {
    asm volatile("ldmatrix.sync.aligned.m8n8.x4.shared.b16 {%0,%1,%2,%3}, [%4];"
                 : "=r"(r[0]), "=r"(r[1]), "=r"(r[2]), "=r"(r[3]) : "r"(addr));
}

// mma.sync m16n8k8 tf32: d += a * b  (fp32 accumulate)
__device__ __forceinline__ void mma_tf32(float& d0, float& d1, float& d2, float& d3,
                                         uint32_t a0, uint32_t a1, uint32_t a2, uint32_t a3,
                                         uint32_t b0, uint32_t b1) {
    asm volatile(
        "mma.sync.aligned.m16n8k8.row.col.f32.tf32.tf32.f32 "
        "{%0,%1,%2,%3}, {%4,%5,%6,%7}, {%8,%9}, {%0,%1,%2,%3};"
        : "+f"(d0), "+f"(d1), "+f"(d2), "+f"(d3)
        : "r"(a0), "r"(a1), "r"(a2), "r"(a3), "r"(b0), "r"(b1));
}

// ============================================================================
// Prep kernel 1: elementwise fp32 -> tf32 (RNA) rounding
// ============================================================================
__global__ void __launch_bounds__(256)
conv_tf32_kernel(const float4* __restrict__ in, float4* __restrict__ out, int n4)
{
    int i = blockIdx.x * blockDim.x + threadIdx.x;
    if (i < n4) {
        float4 v = in[i];
        v.x = __uint_as_float(f2tf32(v.x));
        v.y = __uint_as_float(f2tf32(v.y));
        v.z = __uint_as_float(f2tf32(v.z));
        v.w = __uint_as_float(f2tf32(v.w));
        out[i] = v;
    }
}

// ============================================================================
// Prep kernel 2: W[e][K][N] -> Wt[e][N][K] with tf32 rounding (32x32 smem tile)
// ============================================================================
template <int K, int N>
__global__ void __launch_bounds__(256)
transpose_tf32_kernel(const float* __restrict__ W, float* __restrict__ Wt)
{
    __shared__ float t[32][33];
    const int e  = blockIdx.z;
    const int n0 = blockIdx.x * 32;
    const int k0 = blockIdx.y * 32;
    const float* Win  = W  + (size_t)e * K * N;
    float*       Wout = Wt + (size_t)e * N * K;
    const int tx = threadIdx.x;        // 0..31
    const int ty = threadIdx.y;        // 0..7

    #pragma unroll
    for (int j = 0; j < 4; j++)
        t[ty + 8 * j][tx] = Win[(size_t)(k0 + ty + 8 * j) * N + n0 + tx];
    __syncthreads();
    #pragma unroll
    for (int j = 0; j < 4; j++)
        Wout[(size_t)(n0 + ty + 8 * j) * K + k0 + tx] =
            __uint_as_float(f2tf32(t[tx][ty + 8 * j]));
}

// ============================================================================
// Grouped GEMM (compile-time K/N), all inputs pre-rounded to tf32:
//   A:  [E, NTOK, K] row-major (K contiguous)    -> smem via cp.async
//   Wt: [E, N, K]    row-major (K contiguous!)   -> smem via cp.async
// Per CTA: 128x128 tile, 4 warps (2m x 2n), warp tile 64x64.
// Smem rows 128B, XOR-16B swizzle; ldmatrix -> MMA direct (no cvt anywhere).
// GELU kernels round their output to tf32 (consumed by the next GEMM).
// ============================================================================
template <int K, int N, int NT, int GELU>
__global__ void __launch_bounds__(THREADS, 2)
grouped_gemm_tf32(const float* __restrict__ A, const float* __restrict__ Wt,
                  const float* __restrict__ bias, float* __restrict__ C)
{
    extern __shared__ char smem[];
    const uint32_t sb = smem_u32(smem);
    const int tid  = threadIdx.x;
    const int lane = tid & 31;
    const int wid  = tid >> 5;

    // CTA tile coordinates
    const int bid = blockIdx.x;
    const int e   = bid / (MT * NT);
    const int rr  = bid % (MT * NT);
    const int mt  = rr / NT;
    const int nt  = rr % NT;

    const float* Ae  = A  + (size_t)e * NTOK * K + (size_t)mt * BM * K;
    const float* Wte = Wt + (size_t)e * N * K + (size_t)nt * BN * K;
    float*       Ce  = C  + (size_t)e * NTOK * N + (size_t)mt * BM * N + (size_t)nt * BN;

    // warp layout: 2 warps along M (64 rows each), 2 along N (64 cols each)
    const int mbase = (wid & 1) * 64;
    const int nbase = (wid >> 1) * 64;
    const int g  = lane >> 2;   // group id 0..7
    const int tg = lane & 3;    // thread-in-group 0..3

    // ldmatrix per-lane addressing (proven in R4):
    const uint32_t swz    = lane & 7;
    const uint32_t a_usel = (lane >> 4) & 1;
    const uint32_t b_usel = (lane >> 3) & 1;
    const uint32_t a_rowo = (((lane >> 3) & 1) << 3) + swz;
    const uint32_t b_rowo = (((lane >> 4) & 1) << 3) + swz;

    // loader indices: identical pattern for A and B (both K-contiguous, 128B rows)
    const int row0 = tid >> 3;           // 8 threads/row, rows row0 + 16*i (i<8)
    const int u    = tid & 7;            // 16B unit within 128B row

    // Running source pointers (compile-time strides -> imm offsets)
    const float* aP = Ae  + (size_t)row0 * K + u * 4;
    const float* bP = Wte + (size_t)row0 * K + u * 4;

    // Precomputed smem store addresses (swizzle folded once)
    const uint32_t aSts = sb + row0 * 128 + (((uint32_t)u ^ (row0 & 7)) << 4);
    const uint32_t bSts = aSts + A_BYTES;

    float acc[128];
    #pragma unroll
    for (int i = 0; i < 128; i++) acc[i] = 0.0f;

    constexpr int CH = K / BK;

    // ---------------- prologue: stage chunks 0..STAGES-2 ----------------
    #pragma unroll
    for (int s = 0; s < STAGES - 1; s++) {
        const uint32_t stg = s * STAGE_BYTES;
        #pragma unroll
        for (int i = 0; i < 8; i++)
            cp_async16(aSts + stg + i * 2048, aP + s * BK + (size_t)i * 16 * K);
        #pragma unroll
        for (int i = 0; i < 8; i++)
            cp_async16(bSts + stg + i * 2048, bP + s * BK + (size_t)i * 16 * K);
        cp_commit();
    }
    const float* aRun = aP + (STAGES - 1) * BK;   // next chunk to issue (cn = c+2)
    const float* bRun = bP + (STAGES - 1) * BK;

    // ---------------- main loop ----------------
    #pragma unroll 1
    for (int c = 0; c < CH; c++) {
        cp_wait1();
        __syncthreads();

        const uint32_t stg   = (c % STAGES) * STAGE_BYTES;
        const uint32_t aBase = sb + stg + (mbase + a_rowo) * 128;
        const uint32_t bBase = sb + stg + A_BYTES + (nbase + b_rowo) * 128;

        uint32_t af[2][16], bf[2][16];
        // preload ks=0 fragments; latency hides behind loader block
        {
            const uint32_t xa = ((0 + a_usel) ^ swz) << 4;
            const uint32_t xb = ((0 + b_usel) ^ swz) << 4;
            #pragma unroll
            for (int m2 = 0; m2 < 4; m2++)
                ldsm_x4(&af[0][4 * m2], aBase + m2 * 2048 + xa);
            #pragma unroll
            for (int p = 0; p < 4; p++)
                ldsm_x4(&bf[0][4 * p], bBase + p * 2048 + xb);
        }

        // loader: stage chunk cn = c + STAGES - 1 (pure cp.async now)
        const int cn = c + STAGES - 1;
        if (cn < CH) {
            const uint32_t lstg = (cn % STAGES) * STAGE_BYTES;
            #pragma unroll
            for (int i = 0; i < 8; i++)
                cp_async16(aSts + lstg + i * 2048, aRun + (size_t)i * 16 * K);
            #pragma unroll
            for (int i = 0; i < 8; i++)
                cp_async16(bSts + lstg + i * 2048, bRun + (size_t)i * 16 * K);
        }
        cp_commit();
        aRun += BK;
        bRun += BK;

        // compute: double-buffered ks pipeline, LDSM -> MMA direct
        #pragma unroll
        for (int ks = 0; ks < 4; ks++) {
            const int cur = ks & 1;
            const int nxt = cur ^ 1;
            if (ks < 3) {
                const uint32_t xa = (((uint32_t)(2 * (ks + 1)) + a_usel) ^ swz) << 4;
                const uint32_t xb = (((uint32_t)(2 * (ks + 1)) + b_usel) ^ swz) << 4;
                #pragma unroll
                for (int m2 = 0; m2 < 4; m2++)
                    ldsm_x4(&af[nxt][4 * m2], aBase + m2 * 2048 + xa);
                #pragma unroll
                for (int p = 0; p < 4; p++)
                    ldsm_x4(&bf[nxt][4 * p], bBase + p * 2048 + xb);
            }
            #pragma unroll
            for (int m2 = 0; m2 < 4; m2++) {
                #pragma unroll
                for (int n2 = 0; n2 < 8; n2++) {
                    const int p = n2 >> 1, q = n2 & 1;
                    float* d = &acc[(m2 * 8 + n2) * 4];
                    mma_tf32(d[0], d[1], d[2], d[3],
                             af[cur][4*m2+0], af[cur][4*m2+1],
                             af[cur][4*m2+2], af[cur][4*m2+3],
                             bf[cur][4*p + 2*q], bf[cur][4*p + 2*q + 1]);
                }
            }
        }
    }

    // ---------------- epilogue: bias + (optional) exact GELU ----------------
    // GELU kernels feed the next GEMM -> round output to tf32 here (replaces
    // the cvt the consumer used to do; numerically identical).
    const float* bptr = bias + nt * BN;
    #pragma unroll
    for (int m2 = 0; m2 < 4; m2++) {
        const int r0 = mbase + m2 * 16 + g;
        float* crow = Ce + (size_t)r0 * N;
        #pragma unroll
        for (int n2 = 0; n2 < 8; n2++) {
            const int col = nbase + n2 * 8 + tg * 2;
            const float bv0 = __ldg(bptr + col);
            const float bv1 = __ldg(bptr + col + 1);
            float* d = &acc[(m2 * 8 + n2) * 4];
            float v0 = d[0] + bv0, v1 = d[1] + bv1;
            float v2 = d[2] + bv0, v3 = d[3] + bv1;
            if (GELU) {
                v0 = 0.5f * v0 * (1.0f + erff(v0 * 0.70710678118654752440f));
                v1 = 0.5f * v1 * (1.0f + erff(v1 * 0.70710678118654752440f));
                v2 = 0.5f * v2 * (1.0f + erff(v2 * 0.70710678118654752440f));
                v3 = 0.5f * v3 * (1.0f + erff(v3 * 0.70710678118654752440f));
                v0 = __uint_as_float(f2tf32(v0));
                v1 = __uint_as_float(f2tf32(v1));
                v2 = __uint_as_float(f2tf32(v2));
                v3 = __uint_as_float(f2tf32(v3));
            }
            *reinterpret_cast<float2*>(crow + col)           = make_float2(v0, v1);
            *reinterpret_cast<float2*>(crow + 8 * N + col)   = make_float2(v2, v3);
        }
    }
}

// ============================================================================
// Launch
// ============================================================================
extern "C" void kernel_launch(void* const* d_in, const int* in_sizes, int n_in,
                              void* d_out, int out_size)
{
    const float* x  = (const float*)d_in[0];
    const float* w1 = (const float*)d_in[1];
    const float* w2 = (const float*)d_in[2];
    const float* b1 = (const float*)d_in[3];
    const float* b2 = (const float*)d_in[4];
    float* out = (float*)d_out;

    float *hidden, *xs, *w1t, *w2t;
    cudaGetSymbolAddress((void**)&hidden, g_hidden);
    cudaGetSymbolAddress((void**)&xs,     g_xs);
    cudaGetSymbolAddress((void**)&w1t,    g_w1t);
    cudaGetSymbolAddress((void**)&w2t,    g_w2t);

    cudaFuncSetAttribute(grouped_gemm_tf32<DDIM, HDIM, HDIM / BN, 1>,
                         cudaFuncAttributeMaxDynamicSharedMemorySize, SMEM_TOTAL);
    cudaFuncSetAttribute(grouped_gemm_tf32<HDIM, DDIM, DDIM / BN, 0>,
                         cudaFuncAttributeMaxDynamicSharedMemorySize, SMEM_TOTAL);

    // --- prep: x -> tf32; w1,w2 -> transposed [N][K] tf32 ---
    {
        const int n4 = E_ * NTOK * DDIM / 4;
        conv_tf32_kernel<<<(n4 + 255) / 256, 256>>>(
            (const float4*)x, (float4*)xs, n4);
    }
    transpose_tf32_kernel<DDIM, HDIM>
        <<<dim3(HDIM / 32, DDIM / 32, E_), dim3(32, 8)>>>(w1, w1t);
    transpose_tf32_kernel<HDIM, DDIM>
        <<<dim3(DDIM / 32, HDIM / 32, E_), dim3(32, 8)>>>(w2, w2t);

    // GEMM1 + GELU: [E,2048,1024] @ [E,1024,4096] -> hidden (tf32-rounded)
    grouped_gemm_tf32<DDIM, HDIM, HDIM / BN, 1>
        <<<E_ * MT * (HDIM / BN), THREADS, SMEM_TOTAL>>>(xs, w1t, b1, hidden);

    // GEMM2: hidden @ [E,4096,1024] -> out
    grouped_gemm_tf32<HDIM, DDIM, DDIM / BN, 0>
        <<<E_ * MT * (DDIM / BN), THREADS, SMEM_TOTAL>>>(hidden, w2t, b2, out);
}